// round 10
// baseline (speedup 1.0000x reference)
#include <cuda_runtime.h>
#include <cstdint>

// Problem constants
#define HH 64
#define WW 64
#define CC 3
#define NW 16
#define NPATCH 768
#define NCOMP 16
#define NBIN 200
#define NN 4096
#define DD 12288
#define TT 12288

#define ROWS_PER_BLOCK 512
#define ROW_BLOCKS (NN / ROWS_PER_BLOCK)   // 8
#define ITERS (ROWS_PER_BLOCK / 32)        // 16 (32 rows per block-iteration)

#define LUT_N 512
#define LUT_STRIDE 516       // bytes per comp in shared

// dynamic shared layout (bytes)
#define SXYZD_BYTES (NCOMP * NBIN * 16)        // 51200: float4 (x,y,d,0) tables
#define LUT_OFF     SXYZD_BYTES                // 51200
#define LUT_BYTES   (NCOMP * LUT_STRIDE)       // 8256
#define PV_OFF      (LUT_OFF + LUT_BYTES)      // 59456 (16B aligned)
#define PV_BYTES    (8 * 2 * 32 * 4)           // 2048
#define DB_OFF      (PV_OFF + PV_BYTES)        // 61504
#define DB_BYTES    (8 * 2 * 32 * 4)           // 2048
#define SMEM_TOTAL  (DB_OFF + DB_BYTES)        // 63552

// scratch (device globals: no allocation allowed)
__device__ uint8_t g_lut[TT * LUT_N];                 // 6.3 MB
__device__ float   g_logj_partial[NPATCH * NN];       // 12.6 MB
__device__ float   g_logj_p2[8 * NN];                 // 128 KB

// ---------------------------------------------------------------------------
// LUT build: per spline, lut[i] = count(knots < x0 + i*(xl-x0)/LUT_N)
// ---------------------------------------------------------------------------
__global__ __launch_bounds__(256)
void build_lut_kernel(const float* __restrict__ kx)
{
    __shared__ float s[NCOMP * NBIN];
    const int p = blockIdx.x;
    const int tid = threadIdx.x;
    for (int i = tid; i < NCOMP * NBIN; i += 256) s[i] = kx[p * NCOMP * NBIN + i];
    __syncthreads();

    for (int e = tid; e < NCOMP * LUT_N; e += 256) {
        const int c = e >> 9;
        const int i = e & (LUT_N - 1);
        const float* xx = s + c * NBIN;
        const float x0 = xx[0], xl = xx[NBIN - 1];
        const float gx = x0 + (xl - x0) * ((float)i * (1.0f / LUT_N));
        int lo = 0;
        #pragma unroll
        for (int st = 128; st > 0; st >>= 1) {
            int m = lo + st;
            if (m <= NBIN && xx[m - 1] < gx) lo = m;
        }
        g_lut[(p * NCOMP + c) * LUT_N + i] = (uint8_t)lo;
    }
}

// ---------------------------------------------------------------------------
// Per-element spline evaluation (branchless search on float4 table)
// ---------------------------------------------------------------------------
struct SpOut { float delta; float logd; };

__device__ __forceinline__ SpOut spline_eval(
    float X,
    const float4* __restrict__ tc, const uint8_t* __restrict__ lutc,
    float x0, float xl, float y0, float yl, float d0f, float dlf, float invstep)
{
    int li = __float2int_rd((X - x0) * invstep);
    li = min(max(li, 0), LUT_N - 1);
    int lo = lutc[li];
    lo -= ((lo > 0)    & (tc[max(lo - 1, 0)].x >= X));       // fp-edge back-probe
    lo += ((lo < NBIN) & (tc[min(lo, NBIN - 1)].x < X));     // fwd probe 1
    lo += ((lo < NBIN) & (tc[min(lo, NBIN - 1)].x < X));     // fwd probe 2
    lo += ((lo < NBIN) & (tc[min(lo, NBIN - 1)].x < X));     // fwd probe 3
    const int k = min(max(lo - 1, 0), NBIN - 2);

    const float4 g0 = tc[k];
    const float4 g1 = tc[k + 1];
    const float xk = g0.x, yk = g0.y, dk = g0.z;
    const float xk1 = g1.x, yk1 = g1.y, dk1 = g1.z;

    const float wx   = xk1 - xk;
    const float rwx  = __fdividef(1.f, wx);
    const float s_   = (yk1 - yk) * rwx;
    const float xi   = __saturatef((X - xk) * rwx);
    const float xi1  = 1.f - xi;
    const float xixi1 = xi * xi1;
    const float den  = fmaf(dk + dk1 - 2.f * s_, xixi1, s_);
    const float rden = __fdividef(1.f, den);
    const float num  = fmaf(s_ * xi, xi, dk * xixi1);
    float y    = fmaf(yk1 - yk, num * rden, yk);
    const float dnum = fmaf(dk1 * xi, xi, fmaf(2.f * s_, xixi1, dk * xi1 * xi1));
    float dydx = (s_ * s_) * dnum * (rden * rden);

    const bool below = X < x0;
    const bool above = X > xl;
    if (below) { y = fmaf(X - x0, d0f, y0); dydx = d0f; }
    else if (above) { y = fmaf(X - xl, dlf, yl); dydx = dlf; }

    SpOut o;
    o.delta = y - X;
    o.logd  = __logf(dydx);
    return o;
}

// ---------------------------------------------------------------------------
// Main transport kernel — warp-synchronous, shared-exchange matmuls
// ---------------------------------------------------------------------------
__global__ __launch_bounds__(256, 3)
void patch_transport_kernel(const float* __restrict__ data,
                            const float* __restrict__ wT,
                            const float* __restrict__ kx,
                            const float* __restrict__ ky,
                            const float* __restrict__ kd,
                            float* __restrict__ out)
{
    extern __shared__ char smem[];
    float4*  sxyzd = (float4*)smem;                       // [NCOMP][NBIN]
    uint8_t* slut  = (uint8_t*)(smem + LUT_OFF);
    float*   pvbuf = (float*)(smem + PV_OFF);             // [8 warps][2 chains][32]
    float*   dbuf  = (float*)(smem + DB_OFF);

    const int p   = blockIdx.x;
    const int tid = threadIdx.x;

    // ---- stage knots (float4) + LUT ----
    {
        const int tbase = p * NCOMP * NBIN;
        for (int i = tid; i < NCOMP * NBIN; i += 256) {
            sxyzd[i] = make_float4(kx[tbase + i], ky[tbase + i], kd[tbase + i], 0.f);
        }
        const uint32_t* gl32 = (const uint32_t*)(g_lut + (size_t)p * NCOMP * LUT_N);
        for (int e = tid; e < NCOMP * (LUT_N / 4); e += 256) {
            const int c2 = e >> 7, w = e & 127;
            *(uint32_t*)&slut[c2 * LUT_STRIDE + w * 4] = gl32[c2 * 128 + w];
        }
    }

    const int lane = tid & 31;
    const int wid  = tid >> 5;
    const int half = lane >> 4;
    const int c    = lane & 15;

    // weights in registers: column c (forward), row c (backward)
    float wc[16], wr[16];
    #pragma unroll
    for (int k = 0; k < 16; ++k) wc[k] = wT[p * 256 + k * 16 + c];
    #pragma unroll
    for (int k = 0; k < 16; ++k) wr[k] = wT[p * 256 + c * 16 + k];

    __syncthreads();   // the ONLY block barrier

    // patch -> flat image offset for this thread's element
    const int ph  = p / (NW * CC);
    const int rem = p % (NW * CC);
    const int pw  = rem / CC;
    const int ch  = rem % CC;
    const int base = ph * (4 * WW * CC) + pw * (4 * CC) + ch;
    const int offc = base + (c >> 2) * (WW * CC) + (c & 3) * CC;

    const float4*  __restrict__ tc   = sxyzd + c * NBIN;
    const uint8_t* __restrict__ lutc = slut + c * LUT_STRIDE;

    const float4 t0 = tc[0], tl = tc[NBIN - 1];
    const float x0 = t0.x, y0 = t0.y, d0f = t0.z;
    const float xl = tl.x, yl = tl.y, dlf = tl.z;
    const float invstep = (float)LUT_N / (xl - x0);

    const int rowbase = blockIdx.y * ROWS_PER_BLOCK;
    const int rsub = wid * 2 + half;            // 0..15

    // per-warp exchange slots
    float* pvA_row = pvbuf + wid * 64 + 0 * 32 + half * 16;   // this lane's own row
    float* pvB_row = pvbuf + wid * 64 + 1 * 32 + half * 16;
    float* dA_row  = dbuf  + wid * 64 + 0 * 32 + half * 16;
    float* dB_row  = dbuf  + wid * 64 + 1 * 32 + half * 16;

    int n = rowbase + rsub;                     // chain A row; chain B = n+16
    float pvA = data[(size_t)n * DD + offc];
    float pvB = data[(size_t)(n + 16) * DD + offc];

    for (int it = 0; it < ITERS; ++it) {
        const int nA = n;
        const float paA = pvA, paB = pvB;
        n += 32;
        if (it + 1 < ITERS) {
            pvA = data[(size_t)n * DD + offc];
            pvB = data[(size_t)(n + 16) * DD + offc];
        }

        // exchange patch values through warp-local shared
        pvA_row[c] = paA;
        pvB_row[c] = paB;
        __syncwarp();

        // forward: X = patch_row . w_col(c) via broadcast LDS.128
        const float4* rA = (const float4*)pvA_row;
        const float4* rB = (const float4*)pvB_row;
        float XA = 0.f, XB = 0.f;
        #pragma unroll
        for (int q = 0; q < 4; ++q) {
            const float4 a = rA[q];
            const float4 b = rB[q];
            XA = fmaf(a.x, wc[4*q+0], XA); XA = fmaf(a.y, wc[4*q+1], XA);
            XA = fmaf(a.z, wc[4*q+2], XA); XA = fmaf(a.w, wc[4*q+3], XA);
            XB = fmaf(b.x, wc[4*q+0], XB); XB = fmaf(b.y, wc[4*q+1], XB);
            XB = fmaf(b.z, wc[4*q+2], XB); XB = fmaf(b.w, wc[4*q+3], XB);
        }

        const SpOut oA = spline_eval(XA, tc, lutc, x0, xl, y0, yl, d0f, dlf, invstep);
        const SpOut oB = spline_eval(XB, tc, lutc, x0, xl, y0, yl, d0f, dlf, invstep);

        // reduce logd over the 16 lanes of each half-warp
        float logdA = oA.logd, logdB = oB.logd;
        #pragma unroll
        for (int ofs = 8; ofs > 0; ofs >>= 1) {
            logdA += __shfl_xor_sync(0xffffffffu, logdA, ofs, 16);
            logdB += __shfl_xor_sync(0xffffffffu, logdB, ofs, 16);
        }

        // exchange deltas (separate buffer -> no extra sync before write)
        dA_row[c] = oA.delta;
        dB_row[c] = oB.delta;
        __syncwarp();

        // backward: dpatch[c] = delta_row . wT[p, c, :] via broadcast LDS.128
        const float4* eA = (const float4*)dA_row;
        const float4* eB = (const float4*)dB_row;
        float dpA = 0.f, dpB = 0.f;
        #pragma unroll
        for (int q = 0; q < 4; ++q) {
            const float4 a = eA[q];
            const float4 b = eB[q];
            dpA = fmaf(a.x, wr[4*q+0], dpA); dpA = fmaf(a.y, wr[4*q+1], dpA);
            dpA = fmaf(a.z, wr[4*q+2], dpA); dpA = fmaf(a.w, wr[4*q+3], dpA);
            dpB = fmaf(b.x, wr[4*q+0], dpB); dpB = fmaf(b.y, wr[4*q+1], dpB);
            dpB = fmaf(b.z, wr[4*q+2], dpB); dpB = fmaf(b.w, wr[4*q+3], dpB);
        }

        out[(size_t)nA * DD + offc]        = paA + dpA;
        out[(size_t)(nA + 16) * DD + offc] = paB + dpB;

        if (c == 0) {
            g_logj_partial[p * NN + nA]      = logdA;
            g_logj_partial[p * NN + nA + 16] = logdB;
        }
    }
}

// ---------------------------------------------------------------------------
// log-Jacobian reduction, two stages
// ---------------------------------------------------------------------------
__global__ __launch_bounds__(256)
void logj_reduce1(void)
{
    const int n  = blockIdx.x * 256 + threadIdx.x;
    const int p0 = blockIdx.y * (NPATCH / 8);
    float s0 = 0.f, s1 = 0.f, s2 = 0.f, s3 = 0.f;
    #pragma unroll 4
    for (int p = p0; p < p0 + NPATCH / 8; p += 4) {
        s0 += g_logj_partial[(p + 0) * NN + n];
        s1 += g_logj_partial[(p + 1) * NN + n];
        s2 += g_logj_partial[(p + 2) * NN + n];
        s3 += g_logj_partial[(p + 3) * NN + n];
    }
    g_logj_p2[blockIdx.y * NN + n] = (s0 + s1) + (s2 + s3);
}

__global__ __launch_bounds__(256)
void logj_reduce2(float* __restrict__ out)
{
    const int n = blockIdx.x * 256 + threadIdx.x;
    float s = 0.f;
    #pragma unroll
    for (int g = 0; g < 8; ++g) s += g_logj_p2[g * NN + n];
    out[(size_t)NN * DD + n] = s;
}

extern "C" void kernel_launch(void* const* d_in, const int* in_sizes, int n_in,
                              void* d_out, int out_size)
{
    const float* data = (const float*)d_in[0];
    const float* wT   = (const float*)d_in[1];
    const float* kx   = (const float*)d_in[2];
    const float* ky   = (const float*)d_in[3];
    const float* kd   = (const float*)d_in[4];
    float* out = (float*)d_out;

    cudaFuncSetAttribute(patch_transport_kernel,
                         cudaFuncAttributeMaxDynamicSharedMemorySize, SMEM_TOTAL);

    build_lut_kernel<<<NPATCH, 256>>>(kx);
    dim3 grid(NPATCH, ROW_BLOCKS);
    patch_transport_kernel<<<grid, 256, SMEM_TOTAL>>>(data, wT, kx, ky, kd, out);
    logj_reduce1<<<dim3(NN / 256, 8), 256>>>();
    logj_reduce2<<<NN / 256, 256>>>(out);
}